// round 2
// baseline (speedup 1.0000x reference)
#include <cuda_runtime.h>
#include <math.h>

// Problem constants (B,C,H,W,K) = (32,8,64,64,16)
#define BATCH 32
#define CHW   (8 * 64 * 64)          // 32768 elements per batch
#define N_ELEM (BATCH * CHW)         // 1,048,576
#define KMIX  16
#define TPB   256

__global__ void init_sldj_kernel(const float* __restrict__ sldj_in,
                                 float* __restrict__ sldj_out) {
    int i = threadIdx.x;
    if (i < BATCH) sldj_out[i] = sldj_in[i];
}

// log(1 - exp(x)) for x <= 0, numerically stable
__device__ __forceinline__ float log1mexp(float x) {
    return (x > -0.6931472f) ? logf(-expm1f(x)) : log1pf(-expf(x));
}

__device__ __forceinline__ float softplus_f(float z) {
    // softplus(z) = max(z,0) + log1p(exp(-|z|))
    return fmaxf(z, 0.0f) + log1pf(expf(-fabsf(z)));
}

__global__ void __launch_bounds__(TPB)
coupling_kernel(const float*  __restrict__ x_change,
                const float*  __restrict__ x_id,
                const float*  __restrict__ a,
                const float*  __restrict__ b,
                const float4* __restrict__ pi4,
                const float4* __restrict__ mu4,
                const float4* __restrict__ s4,
                float* __restrict__ out,       // [N_ELEM] transformed x_change
                float* __restrict__ out_id,    // [N_ELEM] passthrough x_id
                float* __restrict__ sldj_out)  // [BATCH]
{
    const int i = blockIdx.x * TPB + threadIdx.x;

    // ---- Front-batched loads for max MLP ----
    const float x  = x_change[i];
    const float av = a[i];
    const float bv = b[i];
    const float xid = x_id[i];

    const int base4 = i * (KMIX / 4);   // float4 index
    float4 p4[4], m4[4], t4[4];
#pragma unroll
    for (int j = 0; j < 4; j++) {
        p4[j] = pi4[base4 + j];
        m4[j] = mu4[base4 + j];
        t4[j] = s4[base4 + j];
    }

    float pv[KMIX], mv[KMIX], sv[KMIX];
#pragma unroll
    for (int j = 0; j < 4; j++) {
        pv[4*j+0] = p4[j].x; pv[4*j+1] = p4[j].y; pv[4*j+2] = p4[j].z; pv[4*j+3] = p4[j].w;
        mv[4*j+0] = m4[j].x; mv[4*j+1] = m4[j].y; mv[4*j+2] = m4[j].z; mv[4*j+3] = m4[j].w;
        sv[4*j+0] = t4[j].x; sv[4*j+1] = t4[j].y; sv[4*j+2] = t4[j].z; sv[4*j+3] = t4[j].w;
    }

    // ---- log_softmax(pi): lp_k = pi_k - logsumexp(pi) ----
    float mpi = pv[0];
#pragma unroll
    for (int k = 1; k < KMIX; k++) mpi = fmaxf(mpi, pv[k]);
    float se = 0.0f;
#pragma unroll
    for (int k = 0; k < KMIX; k++) se += expf(pv[k] - mpi);
    const float lse_pi = mpi + logf(se);

    // ---- per-component terms for log CDF and log PDF ----
    float tc[KMIX], tp[KMIX];
    float mc = -INFINITY, mp = -INFINITY;
#pragma unroll
    for (int k = 0; k < KMIX; k++) {
        const float lp = pv[k] - lse_pi;
        const float z  = (x - mv[k]) * expf(-sv[k]);
        const float sp = softplus_f(z);           // softplus(z)
        const float logsig = z - sp;              // log_sigmoid(z) = -softplus(-z)
        tc[k] = lp + logsig;
        tp[k] = lp + z - sv[k] - 2.0f * sp;       // lp + logistic log-density
        mc = fmaxf(mc, tc[k]);
        mp = fmaxf(mp, tp[k]);
    }
    float sc = 0.0f, sp_ = 0.0f;
#pragma unroll
    for (int k = 0; k < KMIX; k++) {
        sc  += expf(tc[k] - mc);
        sp_ += expf(tp[k] - mp);
    }
    const float log_cdf = mc + logf(sc);
    const float log_pdf = mp + logf(sp_);

    // ---- sigmoid-inverse + affine ----
    const float l1m = log1mexp(log_cdf);          // log(1 - u)
    const float out_v = (log_cdf - l1m + bv) * expf(av);
    const float ldj_elem = log_pdf + (-log_cdf - l1m) + av;  // logistic_ldj + scale_ldj + a

    out[i]    = out_v;
    out_id[i] = xid;

    // ---- per-block reduction of ldj, then one atomic per block ----
    float v = ldj_elem;
#pragma unroll
    for (int off = 16; off > 0; off >>= 1)
        v += __shfl_down_sync(0xFFFFFFFFu, v, off);

    __shared__ float warp_sums[TPB / 32];
    const int lane = threadIdx.x & 31;
    const int wid  = threadIdx.x >> 5;
    if (lane == 0) warp_sums[wid] = v;
    __syncthreads();
    if (wid == 0) {
        float w = (lane < TPB / 32) ? warp_sums[lane] : 0.0f;
#pragma unroll
        for (int off = 4; off > 0; off >>= 1)
            w += __shfl_down_sync(0xFFu, w, off);
        if (lane == 0) {
            const int batch = blockIdx.x / (CHW / TPB);  // 128 blocks per batch
            atomicAdd(&sldj_out[batch], w);
        }
    }
}

extern "C" void kernel_launch(void* const* d_in, const int* in_sizes, int n_in,
                              void* d_out, int out_size) {
    // Inputs (metadata order): x_change, x_id, sldj, a, b, pi, mu, s
    const float* x_change = (const float*)d_in[0];
    const float* x_id     = (const float*)d_in[1];
    const float* sldj     = (const float*)d_in[2];
    const float* a        = (const float*)d_in[3];
    const float* b        = (const float*)d_in[4];
    const float4* pi4     = (const float4*)d_in[5];
    const float4* mu4     = (const float4*)d_in[6];
    const float4* s4      = (const float4*)d_in[7];

    float* out      = (float*)d_out;
    float* out_id   = out + N_ELEM;
    float* sldj_out = out + 2 * N_ELEM;

    init_sldj_kernel<<<1, 32>>>(sldj, sldj_out);
    coupling_kernel<<<N_ELEM / TPB, TPB>>>(x_change, x_id, a, b,
                                           pi4, mu4, s4,
                                           out, out_id, sldj_out);
}

// round 3
// speedup vs baseline: 1.2360x; 1.2360x over previous
#include <cuda_runtime.h>
#include <math.h>

// Problem constants (B,C,H,W,K) = (32,8,64,64,16)
#define BATCH 32
#define CHW   (8 * 64 * 64)          // 32768 elements per batch
#define N_ELEM (BATCH * CHW)         // 1,048,576
#define KMIX  16
#define TPB   256

__global__ void init_sldj_kernel(const float* __restrict__ sldj_in,
                                 float* __restrict__ sldj_out) {
    int i = threadIdx.x;
    if (i < BATCH) sldj_out[i] = sldj_in[i];
}

__global__ void __launch_bounds__(TPB)
coupling_kernel(const float*  __restrict__ x_change,
                const float*  __restrict__ x_id,
                const float*  __restrict__ a,
                const float*  __restrict__ b,
                const float4* __restrict__ pi4,
                const float4* __restrict__ mu4,
                const float4* __restrict__ s4,
                float* __restrict__ out,       // [N_ELEM] transformed x_change
                float* __restrict__ out_id,    // [N_ELEM] passthrough x_id
                float* __restrict__ sldj_out)  // [BATCH]
{
    const int i = blockIdx.x * TPB + threadIdx.x;

    // ---- Front-batched loads for max MLP ----
    const float x   = x_change[i];
    const float av  = a[i];
    const float bv  = b[i];
    const float xid = x_id[i];

    const int base4 = i * (KMIX / 4);   // float4 index
    float4 p4[4], m4[4], t4[4];
#pragma unroll
    for (int j = 0; j < 4; j++) {
        p4[j] = pi4[base4 + j];
        m4[j] = mu4[base4 + j];
        t4[j] = s4[base4 + j];
    }

    // Linear-domain mixture accumulation.
    //   e_k  = exp(pi_k)            (unnormalized softmax weight)
    //   es_k = exp(-s_k)
    //   z_k  = (x - mu_k) * es_k
    //   t_k  = exp(-z_k),  sigma_k = 1/(1+t_k)
    //   S1 = sum e_k*sigma_k            ~ cdf * sum(e)
    //   S0 = sum e_k*t_k*sigma_k        ~ (1-cdf) * sum(e)   (S1+S0 == sum e_k exactly)
    //   P  = sum e_k*es_k*t_k*sigma_k^2 ~ pdf * sum(e)
    float S1 = 0.0f, S0 = 0.0f, P = 0.0f;
#pragma unroll
    for (int j = 0; j < 4; j++) {
        const float pk[4] = {p4[j].x, p4[j].y, p4[j].z, p4[j].w};
        const float mk[4] = {m4[j].x, m4[j].y, m4[j].z, m4[j].w};
        const float sk[4] = {t4[j].x, t4[j].y, t4[j].z, t4[j].w};
#pragma unroll
        for (int q = 0; q < 4; q++) {
            const float ep = __expf(pk[q]);
            const float es = __expf(-sk[q]);
            const float z  = (x - mk[q]) * es;
            const float t  = __expf(-z);
            const float rc = __fdividef(1.0f, 1.0f + t);   // sigma = MUFU.RCP path
            const float r1 = ep * rc;                      // e*sigma
            const float rt = r1 * t;                       // e*(1-sigma)
            S1 += r1;
            S0 += rt;
            P  += rt * (es * rc);                          // e*es*t*sigma^2
        }
    }

    const float lS1 = __logf(S1);
    const float lS0 = __logf(S0);
    const float lSe = __logf(S1 + S0);
    const float lP  = __logf(P);

    // out  = (log_cdf - log(1-u) + b) * exp(a)  =  (log(S1/S0) + b) * exp(a)
    // ldj  = log_pdf + scale_ldj + a  =  lP + lSe - lS1 - lS0 + a
    const float out_v    = (lS1 - lS0 + bv) * __expf(av);
    const float ldj_elem = lP + lSe - lS1 - lS0 + av;

    out[i]    = out_v;
    out_id[i] = xid;

    // ---- per-block reduction of ldj, then one atomic per block ----
    float v = ldj_elem;
#pragma unroll
    for (int off = 16; off > 0; off >>= 1)
        v += __shfl_down_sync(0xFFFFFFFFu, v, off);

    __shared__ float warp_sums[TPB / 32];
    const int lane = threadIdx.x & 31;
    const int wid  = threadIdx.x >> 5;
    if (lane == 0) warp_sums[wid] = v;
    __syncthreads();
    if (wid == 0) {
        float w = (lane < TPB / 32) ? warp_sums[lane] : 0.0f;
#pragma unroll
        for (int off = 4; off > 0; off >>= 1)
            w += __shfl_down_sync(0xFFu, w, off);
        if (lane == 0) {
            const int batch = blockIdx.x / (CHW / TPB);  // 128 blocks per batch
            atomicAdd(&sldj_out[batch], w);
        }
    }
}

extern "C" void kernel_launch(void* const* d_in, const int* in_sizes, int n_in,
                              void* d_out, int out_size) {
    // Inputs (metadata order): x_change, x_id, sldj, a, b, pi, mu, s
    const float* x_change = (const float*)d_in[0];
    const float* x_id     = (const float*)d_in[1];
    const float* sldj     = (const float*)d_in[2];
    const float* a        = (const float*)d_in[3];
    const float* b        = (const float*)d_in[4];
    const float4* pi4     = (const float4*)d_in[5];
    const float4* mu4     = (const float4*)d_in[6];
    const float4* s4      = (const float4*)d_in[7];

    float* out      = (float*)d_out;
    float* out_id   = out + N_ELEM;
    float* sldj_out = out + 2 * N_ELEM;

    init_sldj_kernel<<<1, 32>>>(sldj, sldj_out);
    coupling_kernel<<<N_ELEM / TPB, TPB>>>(x_change, x_id, a, b,
                                           pi4, mu4, s4,
                                           out, out_id, sldj_out);
}